// round 9
// baseline (speedup 1.0000x reference)
#include <cuda_runtime.h>

// Problem constants
#define NN 32
#define CC 64
#define TTT 256
#define VV 25
#define RR 8
#define OO 64
#define SS 3
#define STREAM_ELEMS (NN*OO*TTT*VV)   // 13,107,200
#define NTV (NN*TTT*VV)               // 204,800
#define AROW 652                      // padded a-row per o: 25u*26 + pad (16B-mult)

typedef unsigned long long u64;

__device__ __forceinline__ u64 pack2(float lo, float hi) {
    u64 r; asm("mov.b64 %0,{%1,%2};" : "=l"(r) : "f"(lo), "f"(hi)); return r;
}
__device__ __forceinline__ void unpack2(u64 p, float& lo, float& hi) {
    asm("mov.b64 {%0,%1},%2;" : "=f"(lo), "=f"(hi) : "l"(p));
}
__device__ __forceinline__ void ffma2(u64& d, u64 a, u64 b) {
    asm("fma.rn.f32x2 %0,%1,%2,%0;" : "+l"(d) : "l"(a), "l"(b));
}

// ---------------- scratch ----------------------------------------------------
__device__ float g_xm[2][NN][CC][VV];
__device__ float g_r[2][SS][NN][RR][VV];
__device__ float g_a[2][SS][NN][OO][AROW];         // padded rows (~32 MB)
__device__ float g_sum[2][OO];
__device__ float g_sumsq[2][OO];
__device__ float g_mean[2][OO];
__device__ float g_rstd[2][OO];

// ---------------- K1: mean over T (+ zero stats in block 0) ------------------
__global__ void k_mean(const float* __restrict__ x1, const float* __restrict__ x2) {
    int b   = blockIdx.x;
    int tid = threadIdx.x;
    if (b == 0 && tid < 2*OO) {
        ((float*)g_sum)[tid]   = 0.f;
        ((float*)g_sumsq)[tid] = 0.f;
    }
    int s   = b / (NN*CC);
    int rem = b % (NN*CC);
    const float* x = s ? x2 : x1;
    const float* p = x + (size_t)rem * TTT * VV;
    float acc = 0.f;
    #pragma unroll
    for (int k = 0; k < 8; k++) acc += p[tid + k*800];
    __shared__ float part[800];
    part[tid] = acc;
    __syncthreads();
    if (tid < VV) {
        float sum = 0.f;
        #pragma unroll
        for (int tg = 0; tg < 32; tg++) sum += part[tg*VV + tid];
        g_xm[s][rem/CC][rem%CC][tid] = sum * (1.0f/TTT);
    }
}

// ---------------- K2: r = w·xm + b ------------------------------------------
__global__ void k_r(const float* __restrict__ c1w, const float* __restrict__ c1b,
                    const float* __restrict__ c2w, const float* __restrict__ c2b) {
    int i = blockIdx.x / NN, n = blockIdx.x % NN;
    int tid = threadIdx.x;
    if (tid >= 2*RR*VV) return;
    int s  = tid / (RR*VV);
    int rv = tid % (RR*VV);
    int r  = rv / VV, v = rv % VV;
    const float* w  = s ? c2w : c1w;
    const float* bb = s ? c2b : c1b;
    const float* wrow = w + (i*RR + r)*CC;
    const float* xm   = &g_xm[s][n][0][v];
    float acc = bb[i*RR + r];
    #pragma unroll 8
    for (int c = 0; c < CC; c++) acc += wrow[c] * xm[c*VV];
    g_r[s][i][n][r][v] = acc;
}

// ---------------- K3: rel=tanh(r1-r2); a1,a2 -> padded g_a -------------------
__global__ void k_a(const float* __restrict__ PA, const float* __restrict__ alpha,
                    const float* __restrict__ c5w, const float* __restrict__ c5b,
                    const float* __restrict__ c6w, const float* __restrict__ c6b) {
    int bx = blockIdx.x;                 // o-quarter
    int i  = blockIdx.y / NN, n = blockIdx.y % NN;
    __shared__ float rel[RR][VV*VV];
    __shared__ float r1s[RR][VV], r2s[RR][VV];
    __shared__ u64  wp_s[16*RR];
    int tid = threadIdx.x;
    if (tid < RR*VV) {
        int r = tid/VV, v = tid%VV;
        r1s[r][v] = g_r[0][i][n][r][v];
        r2s[r][v] = g_r[1][i][n][r][v];
    }
    if (tid < 16*RR) {
        int o = tid / RR, r = tid % RR;
        int idx = (i*OO + bx*16 + o)*RR + r;
        wp_s[tid] = pack2(c5w[idx], c6w[idx]);
    }
    __syncthreads();
    {
        int r = 0, uv = tid;
        int u = uv / VV, v = uv - u*VV;
        while (r < RR) {
            rel[r][uv] = tanhf(r1s[r][u] - r2s[r][v]);
            uv += 256;
            if (uv >= VV*VV) { uv -= VV*VV; r++; }
            u = uv / VV; v = uv - u*VV;
        }
    }
    __syncthreads();
    float al = alpha[0];
    {
        int ol = 0, uv = tid;
        while (ol < 16) {
            int o = bx*16 + ol;
            int u = uv / VV, v = uv - u*VV;
            float a1 = c5b[i*OO + o] + PA[i*VV*VV + uv];
            float a2 = c6b[i*OO + o] + al;
            u64 acc = pack2(a1, a2);
            #pragma unroll
            for (int r = 0; r < RR; r++) {
                float rv = rel[r][uv];
                ffma2(acc, wp_s[ol*RR + r], pack2(rv, rv));
            }
            float lo, hi; unpack2(acc, lo, hi);
            g_a[0][i][n][o][u*26 + v] = lo;
            g_a[1][i][n][o][u*26 + v] = hi;
            uv += 256;
            if (uv >= VV*VV) { uv -= VV*VV; ol++; }
        }
    }
}

// ---------------- K4: fused conv1x1 + graph contraction ----------------------
// block = (t-tile 32, o-tile 8, (s,n)); 256 threads, 4 blocks/SM.
// dyn smem:
//   [0)      wsd : u64[64][4]    (w dup pairs)          2048
//   [2048)   bpr : u64[4]                                 32
//   [2080->2112 pad to 16B]
//   [2112)   x3s : f32[8][832]   (conv tile, row 26)   26624
//   [28736)  as_ : f32[8][652]   (a rows, padded)      20864
#define SM_WSD  0
#define SM_BPR  2048
#define SM_X3S  2112
#define SM_AS   28736
#define SMEM_BYTES (28736 + 20864)   // 49600

__global__ void __launch_bounds__(256, 4)
k_main(const float* __restrict__ x1, const float* __restrict__ x2,
       const float* __restrict__ c3w, const float* __restrict__ c3b,
       const float* __restrict__ c4w, const float* __restrict__ c4b,
       float* __restrict__ out) {
    extern __shared__ __align__(16) char smraw[];
    u64*   wsd = (u64*)(smraw + SM_WSD);
    u64*   bpr = (u64*)(smraw + SM_BPR);
    float* x3s = (float*)(smraw + SM_X3S);
    float* as_ = (float*)(smraw + SM_AS);

    int tt0   = blockIdx.x * 32;
    int obase = blockIdx.y * 8;
    int z     = blockIdx.z;
    int s     = z >> 5;
    int n     = z & 31;
    const float* x  = s ? x2  : x1;
    const float* cw = s ? c4w : c3w;
    const float* cb = s ? c4b : c3b;
    float* yout = out + (size_t)s * STREAM_ELEMS;

    int tid  = threadIdx.x;
    int wid  = tid >> 5;                // phase-2: warp -> o in tile (0..7)
    int lane = tid & 31;                // phase-2: lane -> t in tile

    float yacc[VV];
    #pragma unroll
    for (int u = 0; u < VV; u++) yacc[u] = 0.f;

    const float* xbase = x + ((size_t)n*CC)*TTT*VV + (size_t)tt0*VV;

    for (int i = 0; i < SS; i++) {
        __syncthreads();   // prev subset's phase-2 reads done before restage

        // ---- stage: w dup pairs (256 = 1/thread), bias, a-slice (float4 copy)
        {
            int c = tid >> 2, j = tid & 3;
            int ob = (i*OO + obase + 2*j)*CC + c;
            wsd[tid] = pack2(cw[ob], cw[ob + CC]);
        }
        if (tid < 4)
            bpr[tid] = pack2(cb[i*OO + obase + 2*tid], cb[i*OO + obase + 2*tid + 1]);
        {
            const float4* asrc = (const float4*)&g_a[s][i][n][obase][0]; // 8*652 floats
            float4* adst = (float4*)as_;
            #pragma unroll
            for (int q = tid; q < 8*AROW/4; q += 256) adst[q] = asrc[q];
        }
        __syncthreads();

        // ---- phase 1: x3[ol][t][v] = sum_c w·x + b
        // Two sequential position-passes (float2 each) -> acc regs halved
        // vs float4 single-pass; enables 4 blocks/SM.
        if (tid < 200) {
            #pragma unroll
            for (int pass = 0; pass < 2; pass++) {
                u64 acc[2][4];
                #pragma unroll
                for (int e = 0; e < 2; e++)
                    #pragma unroll
                    for (int j = 0; j < 4; j++) acc[e][j] = bpr[j];

                const float* xp = xbase + pass*400 + tid*2;
                #pragma unroll 8
                for (int c = 0; c < CC; c++) {
                    float2 xq = *(const float2*)(xp + (size_t)c*TTT*VV);
                    const ulonglong2* wr = (const ulonglong2*)&wsd[c*4];
                    ulonglong2 wA = wr[0], wB = wr[1];
                    u64 xb0 = pack2(xq.x, xq.x);
                    u64 xb1 = pack2(xq.y, xq.y);
                    ffma2(acc[0][0], xb0, wA.x); ffma2(acc[0][1], xb0, wA.y);
                    ffma2(acc[0][2], xb0, wB.x); ffma2(acc[0][3], xb0, wB.y);
                    ffma2(acc[1][0], xb1, wA.x); ffma2(acc[1][1], xb1, wA.y);
                    ffma2(acc[1][2], xb1, wB.x); ffma2(acc[1][3], xb1, wB.y);
                }
                #pragma unroll
                for (int e = 0; e < 2; e++) {
                    int p = pass*400 + tid*2 + e;   // < 800
                    int t = p / 25, v = p - t*25;
                    int tv = t*26 + v;
                    #pragma unroll
                    for (int j = 0; j < 4; j++) {
                        float lo, hi; unpack2(acc[e][j], lo, hi);
                        x3s[(2*j  )*832 + tv] = lo;
                        x3s[(2*j+1)*832 + tv] = hi;
                    }
                }
            }
        }
        __syncthreads();

        // ---- phase 2: y[t][u] += sum_v a[wid][u][v] * x3[wid][t][v]
        {
            const u64* xrow = (const u64*)&x3s[wid*832 + lane*26];
            u64 xp2[12];
            #pragma unroll
            for (int j = 0; j < 12; j++) xp2[j] = xrow[j];
            float xlast = x3s[wid*832 + lane*26 + 24];
            const float* ga = &as_[wid*AROW];
            #pragma unroll
            for (int u = 0; u < VV; u++) {
                const u64* ar = (const u64*)(ga + u*26);
                u64 accA = 0ull, accB = 0ull;
                #pragma unroll
                for (int j = 0; j < 12; j += 2) {
                    ffma2(accA, ar[j],   xp2[j]);
                    ffma2(accB, ar[j+1], xp2[j+1]);
                }
                float a0, a1, b0, b1;
                unpack2(accA, a0, a1); unpack2(accB, b0, b1);
                yacc[u] += (a0 + a1) + (b0 + b1) + ga[u*26 + 24] * xlast;
            }
        }
    }

    // ---- channel stats from registers
    {
        int o = obase + wid;
        float ls = 0.f, lq = 0.f;
        #pragma unroll
        for (int u = 0; u < VV; u++) { float yv = yacc[u]; ls += yv; lq += yv*yv; }
        #pragma unroll
        for (int off = 16; off; off >>= 1) {
            ls += __shfl_down_sync(0xffffffffu, ls, off);
            lq += __shfl_down_sync(0xffffffffu, lq, off);
        }
        if (lane == 0) {
            atomicAdd(&g_sum[s][o],   ls);
            atomicAdd(&g_sumsq[s][o], lq);
        }
    }

    // ---- stage y through smem, then coalesced float4 store
    __syncthreads();                       // all phase-2 x3s reads complete
    #pragma unroll
    for (int u = 0; u < VV; u++)
        x3s[wid*832 + lane*25 + u] = yacc[u];
    __syncthreads();
    {
        // 8 rows x 800 floats = 1600 float4
        #pragma unroll
        for (int q = tid; q < 1600; q += 256) {
            int ol = q / 200, k4 = q - ol*200;
            float4 val = *(const float4*)&x3s[ol*832 + k4*4];
            float* dst = yout + (size_t)(n*OO + obase + ol)*TTT*VV + tt0*VV + k4*4;
            *(float4*)dst = val;
        }
    }
}

// ---------------- K5 ---------------------------------------------------------
__global__ void k_stats() {
    int i = threadIdx.x;
    if (i < 2*OO) {
        int s = i / OO, o = i % OO;
        float m = g_sum[s][o] * (1.0f/NTV);
        float v = g_sumsq[s][o] * (1.0f/NTV) - m*m;
        g_mean[s][o] = m;
        g_rstd[s][o] = rsqrtf(v + 1e-5f);
    }
}

// ---------------- K6: BN + residual + ReLU -----------------------------------
__global__ void k_bn(const float* __restrict__ x1, const float* __restrict__ x2,
                     const float* __restrict__ bn1w, const float* __restrict__ bn1b,
                     const float* __restrict__ bn2w, const float* __restrict__ bn2b,
                     float* __restrict__ out) {
    const long total4 = 2L * STREAM_ELEMS / 4;
    long stride = (long)gridDim.x * blockDim.x;
    for (long q = (long)blockIdx.x * blockDim.x + threadIdx.x; q < total4; q += stride) {
        long e   = q * 4;
        int  s   = (int)(e / STREAM_ELEMS);
        long rem = e % STREAM_ELEMS;
        int  o   = (int)((rem / (TTT*VV)) % OO);
        const float* bw = s ? bn2w : bn1w;
        const float* bb = s ? bn2b : bn1b;
        const float* xr = s ? x2   : x1;
        float m  = g_mean[s][o], rs = g_rstd[s][o];
        float sc = rs * bw[o];
        float sh = bb[o] - m * sc;
        float4 yv = ((float4*)out)[q];
        float4 xv = ((const float4*)xr)[rem/4];
        yv.x = fmaxf(fmaf(yv.x, sc, sh) + xv.x, 0.f);
        yv.y = fmaxf(fmaf(yv.y, sc, sh) + xv.y, 0.f);
        yv.z = fmaxf(fmaf(yv.z, sc, sh) + xv.z, 0.f);
        yv.w = fmaxf(fmaf(yv.w, sc, sh) + xv.w, 0.f);
        ((float4*)out)[q] = yv;
    }
}

// ---------------- launcher ---------------------------------------------------
extern "C" void kernel_launch(void* const* d_in, const int* in_sizes, int n_in,
                              void* d_out, int out_size) {
    const float* x1    = (const float*)d_in[0];
    const float* x2    = (const float*)d_in[1];
    const float* PA    = (const float*)d_in[2];
    const float* alpha = (const float*)d_in[3];
    const float* c1w   = (const float*)d_in[4];
    const float* c1b   = (const float*)d_in[5];
    const float* c2w   = (const float*)d_in[6];
    const float* c2b   = (const float*)d_in[7];
    const float* c3w   = (const float*)d_in[8];
    const float* c3b   = (const float*)d_in[9];
    const float* c4w   = (const float*)d_in[10];
    const float* c4b   = (const float*)d_in[11];
    const float* c5w   = (const float*)d_in[12];
    const float* c5b   = (const float*)d_in[13];
    const float* c6w   = (const float*)d_in[14];
    const float* c6b   = (const float*)d_in[15];
    const float* bn1w  = (const float*)d_in[16];
    const float* bn1b  = (const float*)d_in[17];
    const float* bn2w  = (const float*)d_in[18];
    const float* bn2b  = (const float*)d_in[19];
    float* out = (float*)d_out;

    cudaFuncSetAttribute(k_main, cudaFuncAttributeMaxDynamicSharedMemorySize, SMEM_BYTES);

    k_mean<<<2*NN*CC, 800>>>(x1, x2);
    k_r<<<SS*NN, 512>>>(c1w, c1b, c2w, c2b);
    k_a<<<dim3(4, SS*NN), 256>>>(PA, alpha, c5w, c5b, c6w, c6b);
    k_main<<<dim3(TTT/32, OO/8, 2*NN), 256, SMEM_BYTES>>>(x1, x2, c3w, c3b, c4w, c4b, out);
    k_stats<<<1, 128>>>();
    k_bn<<<8192, 256>>>(x1, x2, bn1w, bn1b, bn2w, bn2b, out);
}

// round 10
// speedup vs baseline: 1.0155x; 1.0155x over previous
#include <cuda_runtime.h>

// Problem constants
#define NN 32
#define CC 64
#define TTT 256
#define VV 25
#define RR 8
#define OO 64
#define SS 3
#define STREAM_ELEMS (NN*OO*TTT*VV)   // 13,107,200
#define NTV (NN*TTT*VV)               // 204,800
#define AROW 652                      // padded a-row per o (16B-mult)
#define X3ROW 6656                    // padded x3 row per o: 256 t * 26

typedef unsigned long long u64;

__device__ __forceinline__ u64 pack2(float lo, float hi) {
    u64 r; asm("mov.b64 %0,{%1,%2};" : "=l"(r) : "f"(lo), "f"(hi)); return r;
}
__device__ __forceinline__ void unpack2(u64 p, float& lo, float& hi) {
    asm("mov.b64 {%0,%1},%2;" : "=f"(lo), "=f"(hi) : "l"(p));
}
__device__ __forceinline__ void ffma2(u64& d, u64 a, u64 b) {
    asm("fma.rn.f32x2 %0,%1,%2,%0;" : "+l"(d) : "l"(a), "l"(b));
}
__device__ __forceinline__ unsigned to_tf32(float f) {
    unsigned r; asm("cvt.rna.tf32.f32 %0, %1;" : "=r"(r) : "f"(f)); return r;
}

// ---------------- scratch ----------------------------------------------------
__device__ float g_xm[2][NN][CC][VV];
__device__ float g_r[2][SS][NN][RR][VV];
__device__ float g_a[2][SS][NN][OO][AROW];          // ~32 MB
__device__ float g_x3[2][SS][NN][OO][X3ROW];        // ~327 MB conv output, padded
__device__ float g_sum[2][OO];
__device__ float g_sumsq[2][OO];
__device__ float g_mean[2][OO];
__device__ float g_rstd[2][OO];

// ---------------- K1: mean over T (+ zero stats in block 0) ------------------
__global__ void k_mean(const float* __restrict__ x1, const float* __restrict__ x2) {
    int b   = blockIdx.x;
    int tid = threadIdx.x;
    if (b == 0 && tid < 2*OO) {
        ((float*)g_sum)[tid]   = 0.f;
        ((float*)g_sumsq)[tid] = 0.f;
    }
    int s   = b / (NN*CC);
    int rem = b % (NN*CC);
    const float* x = s ? x2 : x1;
    const float* p = x + (size_t)rem * TTT * VV;
    float acc = 0.f;
    #pragma unroll
    for (int k = 0; k < 8; k++) acc += p[tid + k*800];
    __shared__ float part[800];
    part[tid] = acc;
    __syncthreads();
    if (tid < VV) {
        float sum = 0.f;
        #pragma unroll
        for (int tg = 0; tg < 32; tg++) sum += part[tg*VV + tid];
        g_xm[s][rem/CC][rem%CC][tid] = sum * (1.0f/TTT);
    }
}

// ---------------- K2: r = w·xm + b ------------------------------------------
__global__ void k_r(const float* __restrict__ c1w, const float* __restrict__ c1b,
                    const float* __restrict__ c2w, const float* __restrict__ c2b) {
    int i = blockIdx.x / NN, n = blockIdx.x % NN;
    int tid = threadIdx.x;
    if (tid >= 2*RR*VV) return;
    int s  = tid / (RR*VV);
    int rv = tid % (RR*VV);
    int r  = rv / VV, v = rv % VV;
    const float* w  = s ? c2w : c1w;
    const float* bb = s ? c2b : c1b;
    const float* wrow = w + (i*RR + r)*CC;
    const float* xm   = &g_xm[s][n][0][v];
    float acc = bb[i*RR + r];
    #pragma unroll 8
    for (int c = 0; c < CC; c++) acc += wrow[c] * xm[c*VV];
    g_r[s][i][n][r][v] = acc;
}

// ---------------- K3: rel=tanh(r1-r2); a1,a2 -> padded g_a -------------------
__global__ void k_a(const float* __restrict__ PA, const float* __restrict__ alpha,
                    const float* __restrict__ c5w, const float* __restrict__ c5b,
                    const float* __restrict__ c6w, const float* __restrict__ c6b) {
    int bx = blockIdx.x;                 // o-quarter
    int i  = blockIdx.y / NN, n = blockIdx.y % NN;
    __shared__ float rel[RR][VV*VV];
    __shared__ float r1s[RR][VV], r2s[RR][VV];
    __shared__ u64  wp_s[16*RR];
    int tid = threadIdx.x;
    if (tid < RR*VV) {
        int r = tid/VV, v = tid%VV;
        r1s[r][v] = g_r[0][i][n][r][v];
        r2s[r][v] = g_r[1][i][n][r][v];
    }
    if (tid < 16*RR) {
        int o = tid / RR, r = tid % RR;
        int idx = (i*OO + bx*16 + o)*RR + r;
        wp_s[tid] = pack2(c5w[idx], c6w[idx]);
    }
    __syncthreads();
    {
        int r = 0, uv = tid;
        int u = uv / VV, v = uv - u*VV;
        while (r < RR) {
            rel[r][uv] = tanhf(r1s[r][u] - r2s[r][v]);
            uv += 256;
            if (uv >= VV*VV) { uv -= VV*VV; r++; }
            u = uv / VV; v = uv - u*VV;
        }
    }
    __syncthreads();
    float al = alpha[0];
    {
        int ol = 0, uv = tid;
        while (ol < 16) {
            int o = bx*16 + ol;
            int u = uv / VV, v = uv - u*VV;
            float a1 = c5b[i*OO + o] + PA[i*VV*VV + uv];
            float a2 = c6b[i*OO + o] + al;
            u64 acc = pack2(a1, a2);
            #pragma unroll
            for (int r = 0; r < RR; r++) {
                float rv = rel[r][uv];
                ffma2(acc, wp_s[ol*RR + r], pack2(rv, rv));
            }
            float lo, hi; unpack2(acc, lo, hi);
            g_a[0][i][n][o][u*26 + v] = lo;
            g_a[1][i][n][o][u*26 + v] = hi;
            uv += 256;
            if (uv >= VV*VV) { uv -= VV*VV; ol++; }
        }
    }
}

// ---------------- K_CONV: conv1x1 via tf32 mma.sync --------------------------
// Grid (16 tv-chunks of 400, NN, 2). Block 512 = 16 warps.
// GEMM per (s,n,chunk): D[m=tv(400)][nn=o(64)] = X^T[400x64c] * W^T[64c x 64o], 3 subsets.
// Warp wid: nt = wid&7 (8-o tile), mhalf = wid>>3 (m-tiles 0..12 / 13..24).
// smem: xs[64c][408]  (pitch 408 = 24 mod 32 -> conflict-free A-frag loads)
//       x3s[64o][420] (scatter target, then coalesced f4 store to g_x3)
#define XS_PITCH  408
#define X3S_PITCH 420
#define CONV_SMEM ((64*XS_PITCH + 64*X3S_PITCH)*4)   // 211968

__global__ void __launch_bounds__(512, 1)
k_conv(const float* __restrict__ x1, const float* __restrict__ x2,
       const float* __restrict__ c3w, const float* __restrict__ c3b,
       const float* __restrict__ c4w, const float* __restrict__ c4b) {
    extern __shared__ __align__(16) float cs[];
    float* xs  = cs;                     // [64][408]
    float* x3s = cs + 64*XS_PITCH;       // [64][420]

    int base = blockIdx.x * 400;         // tv chunk base (16 t exactly)
    int n    = blockIdx.y;
    int s    = blockIdx.z;
    const float* x  = s ? x2  : x1;
    const float* cw = s ? c4w : c3w;
    const float* cb = s ? c4b : c3b;

    int tid  = threadIdx.x;
    int wid  = tid >> 5, lane = tid & 31;
    int nt    = wid & 7;                 // o-tile (8 o)
    int mhalf = wid >> 3;
    int mtStart = mhalf ? 13 : 0;
    int mtCount = mhalf ? 12 : 13;
    int tig = lane & 3, grp = lane >> 2;

    // ---- stage X chunk: xs[c][0..399] = x[n][c][base..base+400)
    for (int p4 = tid; p4 < 6400; p4 += 512) {
        int c = p4 / 100, pos = (p4 - c*100) * 4;
        *(float4*)&xs[c*XS_PITCH + pos] =
            *(const float4*)(x + ((size_t)(n*CC + c))*TTT*VV + base + pos);
    }
    __syncthreads();

    int tpad0 = (base/25)*26;            // padded output base (base%25==0)

    for (int i = 0; i < SS; i++) {
        // ---- B-fragments (W) + bias for this warp's 8-o tile
        unsigned B0[8], B1[8];
        #pragma unroll
        for (int k = 0; k < 8; k++) {
            B0[k] = to_tf32(cw[(i*OO + nt*8 + grp)*CC + k*8 + tig]);
            B1[k] = to_tf32(cw[(i*OO + nt*8 + grp)*CC + k*8 + tig + 4]);
        }
        float blo = cb[i*OO + nt*8 + 2*tig];
        float bhi = cb[i*OO + nt*8 + 2*tig + 1];

        // ---- mma over this warp's m-tiles
        for (int mi = 0; mi < mtCount; mi++) {
            int m0 = (mtStart + mi) * 16;
            float d0 = blo, d1 = bhi, d2 = blo, d3 = bhi;
            #pragma unroll
            for (int k = 0; k < 8; k++) {
                unsigned a0 = to_tf32(xs[(k*8 + tig    )*XS_PITCH + m0 +     grp]);
                unsigned a1 = to_tf32(xs[(k*8 + tig    )*XS_PITCH + m0 + 8 + grp]);
                unsigned a2 = to_tf32(xs[(k*8 + tig + 4)*XS_PITCH + m0 +     grp]);
                unsigned a3 = to_tf32(xs[(k*8 + tig + 4)*XS_PITCH + m0 + 8 + grp]);
                asm volatile(
                    "mma.sync.aligned.m16n8k8.row.col.f32.tf32.tf32.f32 "
                    "{%0,%1,%2,%3},{%4,%5,%6,%7},{%8,%9},{%0,%1,%2,%3};\n"
                    : "+f"(d0), "+f"(d1), "+f"(d2), "+f"(d3)
                    : "r"(a0), "r"(a1), "r"(a2), "r"(a3), "r"(B0[k]), "r"(B1[k]));
            }
            // scatter D into padded x3s rows
            int oc = nt*8 + 2*tig;
            int tv0 = m0 + grp;
            int t0 = (tv0 * 5243) >> 17; int v0 = tv0 - t0*25;
            x3s[ oc     *X3S_PITCH + t0*26 + v0] = d0;
            x3s[(oc + 1)*X3S_PITCH + t0*26 + v0] = d1;
            int tv1 = tv0 + 8;
            int t1 = (tv1 * 5243) >> 17; int v1 = tv1 - t1*25;
            x3s[ oc     *X3S_PITCH + t1*26 + v1] = d2;
            x3s[(oc + 1)*X3S_PITCH + t1*26 + v1] = d3;
        }
        __syncthreads();

        // ---- coalesced store: x3s[o][0..415] -> g_x3[s][i][n][o][tpad0..+416)
        {
            float* dstb = &g_x3[s][i][n][0][0];
            for (int p4 = tid; p4 < 6656; p4 += 512) {
                int o = p4 / 104, pos = (p4 - o*104) * 4;
                *(float4*)(dstb + (size_t)o*X3ROW + tpad0 + pos) =
                    *(float4*)&x3s[o*X3S_PITCH + pos];
            }
        }
        __syncthreads();
    }
}

// ---------------- K_P2: graph contraction (phase-2) --------------------------
// block = (t-tile 32, o-tile 8, (s,n)); 256 threads, 4 blocks/SM.
// smem: x3s f32[8][832] (26624) + as_ f32[8][652] (20864) = 47488
#define P2_X3S  0
#define P2_AS   26624
#define P2_SMEM (26624 + 20864)

__global__ void __launch_bounds__(256, 4)
k_p2(float* __restrict__ out) {
    extern __shared__ __align__(16) char smraw[];
    float* x3s = (float*)(smraw + P2_X3S);
    float* as_ = (float*)(smraw + P2_AS);

    int tt0   = blockIdx.x * 32;
    int obase = blockIdx.y * 8;
    int z     = blockIdx.z;
    int s     = z >> 5;
    int n     = z & 31;
    float* yout = out + (size_t)s * STREAM_ELEMS;

    int tid  = threadIdx.x;
    int wid  = tid >> 5;                // warp -> o in tile
    int lane = tid & 31;                // lane -> t in tile

    float yacc[VV];
    #pragma unroll
    for (int u = 0; u < VV; u++) yacc[u] = 0.f;

    for (int i = 0; i < SS; i++) {
        __syncthreads();

        // stage x3 tile (pure float4 copy; g_x3 rows are pre-padded)
        {
            const float* srcb = &g_x3[s][i][n][obase][0] + (size_t)tt0*26;
            for (int q = tid; q < 1664; q += 256) {
                int ol = q / 208, pos = (q - ol*208) * 4;
                *(float4*)&x3s[ol*832 + pos] =
                    *(const float4*)(srcb + (size_t)ol*X3ROW + pos);
            }
        }
        // stage a slice (pre-padded)
        {
            const float4* asrc = (const float4*)&g_a[s][i][n][obase][0];
            float4* adst = (float4*)as_;
            #pragma unroll
            for (int q = tid; q < 8*AROW/4; q += 256) adst[q] = asrc[q];
        }
        __syncthreads();

        // phase-2: y[t][u] += sum_v a[wid][u][v] * x3[wid][t][v]
        {
            const u64* xrow = (const u64*)&x3s[wid*832 + lane*26];
            u64 xp2[12];
            #pragma unroll
            for (int j = 0; j < 12; j++) xp2[j] = xrow[j];
            float xlast = x3s[wid*832 + lane*26 + 24];
            const float* ga = &as_[wid*AROW];
            #pragma unroll
            for (int u = 0; u < VV; u++) {
                const u64* ar = (const u64*)(ga + u*26);
                u64 accA = 0ull, accB = 0ull;
                #pragma unroll
                for (int j = 0; j < 12; j += 2) {
                    ffma2(accA, ar[j],   xp2[j]);
                    ffma2(accB, ar[j+1], xp2[j+1]);
                }
                float a0, a1, b0, b1;
                unpack2(accA, a0, a1); unpack2(accB, b0, b1);
                yacc[u] += (a0 + a1) + (b0 + b1) + ga[u*26 + 24] * xlast;
            }
        }
    }

    // channel stats
    {
        int o = obase + wid;
        float ls = 0.f, lq = 0.f;
        #pragma unroll
        for (int u = 0; u < VV; u++) { float yv = yacc[u]; ls += yv; lq += yv*yv; }
        #pragma unroll
        for (int off = 16; off; off >>= 1) {
            ls += __shfl_down_sync(0xffffffffu, ls, off);
            lq += __shfl_down_sync(0xffffffffu, lq, off);
        }
        if (lane == 0) {
            atomicAdd(&g_sum[s][o],   ls);
            atomicAdd(&g_sumsq[s][o], lq);
        }
    }

    // stage y through smem, then coalesced float4 store
    __syncthreads();
    #pragma unroll
    for (int u = 0; u < VV; u++)
        x3s[wid*832 + lane*25 + u] = yacc[u];
    __syncthreads();
    {
        #pragma unroll
        for (int q = tid; q < 1600; q += 256) {
            int ol = q / 200, k4 = q - ol*200;
            float4 val = *(const float4*)&x3s[ol*832 + k4*4];
            float* dst = yout + (size_t)(n*OO + obase + ol)*TTT*VV + tt0*VV + k4*4;
            *(float4*)dst = val;
        }
    }
}

// ---------------- K5 ---------------------------------------------------------
__global__ void k_stats() {
    int i = threadIdx.x;
    if (i < 2*OO) {
        int s = i / OO, o = i % OO;
        float m = g_sum[s][o] * (1.0f/NTV);
        float v = g_sumsq[s][o] * (1.0f/NTV) - m*m;
        g_mean[s][o] = m;
        g_rstd[s][o] = rsqrtf(v + 1e-5f);
    }
}

// ---------------- K6: BN + residual + ReLU -----------------------------------
__global__ void k_bn(const float* __restrict__ x1, const float* __restrict__ x2,
                     const float* __restrict__ bn1w, const float* __restrict__ bn1b,
                     const float* __restrict__ bn2w, const float* __restrict__ bn2b,
                     float* __restrict__ out) {
    const long total4 = 2L * STREAM_ELEMS / 4;
    long stride = (long)gridDim.x * blockDim.x;
    for (long q = (long)blockIdx.x * blockDim.x + threadIdx.x; q < total4; q += stride) {
        long e   = q * 4;
        int  s   = (int)(e / STREAM_ELEMS);
        long rem = e % STREAM_ELEMS;
        int  o   = (int)((rem / (TTT*VV)) % OO);
        const float* bw = s ? bn2w : bn1w;
        const float* bb = s ? bn2b : bn1b;
        const float* xr = s ? x2   : x1;
        float m  = g_mean[s][o], rs = g_rstd[s][o];
        float sc = rs * bw[o];
        float sh = bb[o] - m * sc;
        float4 yv = ((float4*)out)[q];
        float4 xv = ((const float4*)xr)[rem/4];
        yv.x = fmaxf(fmaf(yv.x, sc, sh) + xv.x, 0.f);
        yv.y = fmaxf(fmaf(yv.y, sc, sh) + xv.y, 0.f);
        yv.z = fmaxf(fmaf(yv.z, sc, sh) + xv.z, 0.f);
        yv.w = fmaxf(fmaf(yv.w, sc, sh) + xv.w, 0.f);
        ((float4*)out)[q] = yv;
    }
}

// ---------------- launcher ---------------------------------------------------
extern "C" void kernel_launch(void* const* d_in, const int* in_sizes, int n_in,
                              void* d_out, int out_size) {
    const float* x1    = (const float*)d_in[0];
    const float* x2    = (const float*)d_in[1];
    const float* PA    = (const float*)d_in[2];
    const float* alpha = (const float*)d_in[3];
    const float* c1w   = (const float*)d_in[4];
    const float* c1b   = (const float*)d_in[5];
    const float* c2w   = (const float*)d_in[6];
    const float* c2b   = (const float*)d_in[7];
    const float* c3w   = (const float*)d_in[8];
    const float* c3b   = (const float*)d_in[9];
    const float* c4w   = (const float*)d_in[10];
    const float* c4b   = (const float*)d_in[11];
    const float* c5w   = (const float*)d_in[12];
    const float* c5b   = (const float*)d_in[13];
    const float* c6w   = (const float*)d_in[14];
    const float* c6b   = (const float*)d_in[15];
    const float* bn1w  = (const float*)d_in[16];
    const float* bn1b  = (const float*)d_in[17];
    const float* bn2w  = (const float*)d_in[18];
    const float* bn2b  = (const float*)d_in[19];
    float* out = (float*)d_out;

    cudaFuncSetAttribute(k_conv, cudaFuncAttributeMaxDynamicSharedMemorySize, CONV_SMEM);
    cudaFuncSetAttribute(k_p2,   cudaFuncAttributeMaxDynamicSharedMemorySize, P2_SMEM);

    k_mean<<<2*NN*CC, 800>>>(x1, x2);
    k_r<<<SS*NN, 512>>>(c1w, c1b, c2w, c2b);
    k_a<<<dim3(4, SS*NN), 256>>>(PA, alpha, c5w, c5b, c6w, c6b);
    k_conv<<<dim3(16, NN, 2), 512, CONV_SMEM>>>(x1, x2, c3w, c3b, c4w, c4b);
    k_p2<<<dim3(TTT/32, OO/8, 2*NN), 256, P2_SMEM>>>(out);
    k_stats<<<1, 128>>>();
    k_bn<<<8192, 256>>>(x1, x2, bn1w, bn1b, bn2w, bn2b, out);
}

// round 11
// speedup vs baseline: 1.0216x; 1.0060x over previous
#include <cuda_runtime.h>

// Problem constants
#define NN 32
#define CC 64
#define TTT 256
#define VV 25
#define RR 8
#define OO 64
#define SS 3
#define STREAM_ELEMS (NN*OO*TTT*VV)   // 13,107,200
#define NTV (NN*TTT*VV)               // 204,800
#define AROW 652                      // padded a-row per o (16B-mult)
#define X3ROW 6656                    // padded x3 row per o: 256 t * 26

typedef unsigned long long u64;

__device__ __forceinline__ u64 pack2(float lo, float hi) {
    u64 r; asm("mov.b64 %0,{%1,%2};" : "=l"(r) : "f"(lo), "f"(hi)); return r;
}
__device__ __forceinline__ void unpack2(u64 p, float& lo, float& hi) {
    asm("mov.b64 {%0,%1},%2;" : "=f"(lo), "=f"(hi) : "l"(p));
}
__device__ __forceinline__ void ffma2(u64& d, u64 a, u64 b) {
    asm("fma.rn.f32x2 %0,%1,%2,%0;" : "+l"(d) : "l"(a), "l"(b));
}
__device__ __forceinline__ unsigned to_tf32(float f) {
    unsigned r; asm("cvt.rna.tf32.f32 %0, %1;" : "=r"(r) : "f"(f)); return r;
}
__device__ __forceinline__ void mma_tf32(float& d0, float& d1, float& d2, float& d3,
                                         unsigned a0, unsigned a1, unsigned a2, unsigned a3,
                                         unsigned b0, unsigned b1) {
    asm volatile(
        "mma.sync.aligned.m16n8k8.row.col.f32.tf32.tf32.f32 "
        "{%0,%1,%2,%3},{%4,%5,%6,%7},{%8,%9},{%0,%1,%2,%3};\n"
        : "+f"(d0), "+f"(d1), "+f"(d2), "+f"(d3)
        : "r"(a0), "r"(a1), "r"(a2), "r"(a3), "r"(b0), "r"(b1));
}

// ---------------- scratch ----------------------------------------------------
__device__ float g_xm[2][NN][CC][VV];
__device__ float g_r[2][SS][NN][RR][VV];
__device__ float g_a[2][SS][NN][OO][AROW];          // ~32 MB
__device__ float g_x3[2][SS][NN][OO][X3ROW];        // ~327 MB conv output, padded
__device__ float g_sum[2][OO];
__device__ float g_sumsq[2][OO];
__device__ float g_mean[2][OO];
__device__ float g_rstd[2][OO];

// ---------------- K1: mean over T (+ zero stats in block 0) ------------------
__global__ void k_mean(const float* __restrict__ x1, const float* __restrict__ x2) {
    int b   = blockIdx.x;
    int tid = threadIdx.x;
    if (b == 0 && tid < 2*OO) {
        ((float*)g_sum)[tid]   = 0.f;
        ((float*)g_sumsq)[tid] = 0.f;
    }
    int s   = b / (NN*CC);
    int rem = b % (NN*CC);
    const float* x = s ? x2 : x1;
    const float* p = x + (size_t)rem * TTT * VV;
    float acc = 0.f;
    #pragma unroll
    for (int k = 0; k < 8; k++) acc += p[tid + k*800];
    __shared__ float part[800];
    part[tid] = acc;
    __syncthreads();
    if (tid < VV) {
        float sum = 0.f;
        #pragma unroll
        for (int tg = 0; tg < 32; tg++) sum += part[tg*VV + tid];
        g_xm[s][rem/CC][rem%CC][tid] = sum * (1.0f/TTT);
    }
}

// ---------------- K2: r = w·xm + b ------------------------------------------
__global__ void k_r(const float* __restrict__ c1w, const float* __restrict__ c1b,
                    const float* __restrict__ c2w, const float* __restrict__ c2b) {
    int i = blockIdx.x / NN, n = blockIdx.x % NN;
    int tid = threadIdx.x;
    if (tid >= 2*RR*VV) return;
    int s  = tid / (RR*VV);
    int rv = tid % (RR*VV);
    int r  = rv / VV, v = rv % VV;
    const float* w  = s ? c2w : c1w;
    const float* bb = s ? c2b : c1b;
    const float* wrow = w + (i*RR + r)*CC;
    const float* xm   = &g_xm[s][n][0][v];
    float acc = bb[i*RR + r];
    #pragma unroll 8
    for (int c = 0; c < CC; c++) acc += wrow[c] * xm[c*VV];
    g_r[s][i][n][r][v] = acc;
}

// ---------------- K3: rel=tanh(r1-r2); a1,a2 -> padded g_a -------------------
__global__ void k_a(const float* __restrict__ PA, const float* __restrict__ alpha,
                    const float* __restrict__ c5w, const float* __restrict__ c5b,
                    const float* __restrict__ c6w, const float* __restrict__ c6b) {
    int bx = blockIdx.x;                 // o-quarter
    int i  = blockIdx.y / NN, n = blockIdx.y % NN;
    __shared__ float rel[RR][VV*VV];
    __shared__ float r1s[RR][VV], r2s[RR][VV];
    __shared__ u64  wp_s[16*RR];
    int tid = threadIdx.x;
    if (tid < RR*VV) {
        int r = tid/VV, v = tid%VV;
        r1s[r][v] = g_r[0][i][n][r][v];
        r2s[r][v] = g_r[1][i][n][r][v];
    }
    if (tid < 16*RR) {
        int o = tid / RR, r = tid % RR;
        int idx = (i*OO + bx*16 + o)*RR + r;
        wp_s[tid] = pack2(c5w[idx], c6w[idx]);
    }
    __syncthreads();
    {
        int r = 0, uv = tid;
        int u = uv / VV, v = uv - u*VV;
        while (r < RR) {
            rel[r][uv] = tanhf(r1s[r][u] - r2s[r][v]);
            uv += 256;
            if (uv >= VV*VV) { uv -= VV*VV; r++; }
            u = uv / VV; v = uv - u*VV;
        }
    }
    __syncthreads();
    float al = alpha[0];
    {
        int ol = 0, uv = tid;
        while (ol < 16) {
            int o = bx*16 + ol;
            int u = uv / VV, v = uv - u*VV;
            float a1 = c5b[i*OO + o] + PA[i*VV*VV + uv];
            float a2 = c6b[i*OO + o] + al;
            u64 acc = pack2(a1, a2);
            #pragma unroll
            for (int r = 0; r < RR; r++) {
                float rv = rel[r][uv];
                ffma2(acc, wp_s[ol*RR + r], pack2(rv, rv));
            }
            float lo, hi; unpack2(acc, lo, hi);
            g_a[0][i][n][o][u*26 + v] = lo;
            g_a[1][i][n][o][u*26 + v] = hi;
            uv += 256;
            if (uv >= VV*VV) { uv -= VV*VV; ol++; }
        }
    }
}

// ---------------- K_CONV: conv1x1 via tf32 mma.sync --------------------------
// Grid (16 tv-chunks of 400, NN, 2). Block 512 = 16 warps, 2 blocks/SM.
// Chunk 400 = exactly 25 m16-tiles; no partial tiles.
// A-frags shared across subsets: pass 1 = subsets {0,1} (2 mma / A-load),
// pass 2 = subset {2}. D scattered directly to padded g_x3 (no smem buffer).
// smem: xs[64c][408] only (pitch 408 % 32 == 24 -> conflict-free A loads).
#define XS_PITCH  408
#define CONV_SMEM (64*XS_PITCH*4)      // 104448

__global__ void __launch_bounds__(512, 2)
k_conv(const float* __restrict__ x1, const float* __restrict__ x2,
       const float* __restrict__ c3w, const float* __restrict__ c3b,
       const float* __restrict__ c4w, const float* __restrict__ c4b) {
    extern __shared__ __align__(16) float xs[];    // [64][408]

    int base = blockIdx.x * 400;         // tv chunk base
    int n    = blockIdx.y;
    int s    = blockIdx.z;
    const float* x  = s ? x2  : x1;
    const float* cw = s ? c4w : c3w;
    const float* cb = s ? c4b : c3b;

    int tid  = threadIdx.x;
    int wid  = tid >> 5, lane = tid & 31;
    int nt    = wid & 7;                 // o-tile (8 o)
    int mhalf = wid >> 3;
    int mtStart = mhalf ? 13 : 0;
    int mtCount = mhalf ? 12 : 13;
    int tig = lane & 3, grp = lane >> 2;
    int oc  = nt*8 + 2*tig;

    // ---- stage X chunk: xs[c][0..399] = x[n][c][base..base+400)
    for (int p4 = tid; p4 < 6400; p4 += 512) {
        int c = p4 / 100, pos = (p4 - c*100) * 4;
        *(float4*)&xs[c*XS_PITCH + pos] =
            *(const float4*)(x + ((size_t)(n*CC + c))*TTT*VV + base + pos);
    }
    __syncthreads();

    int tpad0 = (base/25)*26;            // padded output base

    // ================= pass 1: subsets 0 and 1 =================
    {
        unsigned B00[8], B01[8], B10[8], B11[8];
        #pragma unroll
        for (int k = 0; k < 8; k++) {
            B00[k] = to_tf32(cw[(0*OO + nt*8 + grp)*CC + k*8 + tig]);
            B01[k] = to_tf32(cw[(0*OO + nt*8 + grp)*CC + k*8 + tig + 4]);
            B10[k] = to_tf32(cw[(1*OO + nt*8 + grp)*CC + k*8 + tig]);
            B11[k] = to_tf32(cw[(1*OO + nt*8 + grp)*CC + k*8 + tig + 4]);
        }
        float b0lo = cb[0*OO + oc], b0hi = cb[0*OO + oc + 1];
        float b1lo = cb[1*OO + oc], b1hi = cb[1*OO + oc + 1];
        float* dst0 = &g_x3[s][0][n][0][0] + tpad0;
        float* dst1 = &g_x3[s][1][n][0][0] + tpad0;

        for (int mi = 0; mi < mtCount; mi++) {
            int m0 = (mtStart + mi) * 16;
            float d00 = b0lo, d01 = b0hi, d02 = b0lo, d03 = b0hi;
            float d10 = b1lo, d11 = b1hi, d12 = b1lo, d13 = b1hi;
            #pragma unroll
            for (int k = 0; k < 8; k++) {
                unsigned a0 = to_tf32(xs[(k*8 + tig    )*XS_PITCH + m0 +     grp]);
                unsigned a1 = to_tf32(xs[(k*8 + tig    )*XS_PITCH + m0 + 8 + grp]);
                unsigned a2 = to_tf32(xs[(k*8 + tig + 4)*XS_PITCH + m0 +     grp]);
                unsigned a3 = to_tf32(xs[(k*8 + tig + 4)*XS_PITCH + m0 + 8 + grp]);
                mma_tf32(d00, d01, d02, d03, a0, a1, a2, a3, B00[k], B01[k]);
                mma_tf32(d10, d11, d12, d13, a0, a1, a2, a3, B10[k], B11[k]);
            }
            int tv0 = m0 + grp;
            int t0 = (tv0 * 5243) >> 17; int off0 = t0*26 + (tv0 - t0*25);
            int tv1 = tv0 + 8;
            int t1 = (tv1 * 5243) >> 17; int off1 = t1*26 + (tv1 - t1*25);
            size_t r0 = (size_t)oc*X3ROW, r1 = (size_t)(oc+1)*X3ROW;
            dst0[r0 + off0] = d00; dst0[r1 + off0] = d01;
            dst0[r0 + off1] = d02; dst0[r1 + off1] = d03;
            dst1[r0 + off0] = d10; dst1[r1 + off0] = d11;
            dst1[r0 + off1] = d12; dst1[r1 + off1] = d13;
        }
    }

    // ================= pass 2: subset 2 =================
    {
        unsigned B0[8], B1[8];
        #pragma unroll
        for (int k = 0; k < 8; k++) {
            B0[k] = to_tf32(cw[(2*OO + nt*8 + grp)*CC + k*8 + tig]);
            B1[k] = to_tf32(cw[(2*OO + nt*8 + grp)*CC + k*8 + tig + 4]);
        }
        float blo = cb[2*OO + oc], bhi = cb[2*OO + oc + 1];
        float* dst2 = &g_x3[s][2][n][0][0] + tpad0;

        for (int mi = 0; mi < mtCount; mi++) {
            int m0 = (mtStart + mi) * 16;
            float d0 = blo, d1 = bhi, d2 = blo, d3 = bhi;
            #pragma unroll
            for (int k = 0; k < 8; k++) {
                unsigned a0 = to_tf32(xs[(k*8 + tig    )*XS_PITCH + m0 +     grp]);
                unsigned a1 = to_tf32(xs[(k*8 + tig    )*XS_PITCH + m0 + 8 + grp]);
                unsigned a2 = to_tf32(xs[(k*8 + tig + 4)*XS_PITCH + m0 +     grp]);
                unsigned a3 = to_tf32(xs[(k*8 + tig + 4)*XS_PITCH + m0 + 8 + grp]);
                mma_tf32(d0, d1, d2, d3, a0, a1, a2, a3, B0[k], B1[k]);
            }
            int tv0 = m0 + grp;
            int t0 = (tv0 * 5243) >> 17; int off0 = t0*26 + (tv0 - t0*25);
            int tv1 = tv0 + 8;
            int t1 = (tv1 * 5243) >> 17; int off1 = t1*26 + (tv1 - t1*25);
            size_t r0 = (size_t)oc*X3ROW, r1 = (size_t)(oc+1)*X3ROW;
            dst2[r0 + off0] = d0; dst2[r1 + off0] = d1;
            dst2[r0 + off1] = d2; dst2[r1 + off1] = d3;
        }
    }
}

// ---------------- K_P2: graph contraction (phase-2) --------------------------
// block = (t-tile 32, o-tile 8, (s,n)); 256 threads, 4 blocks/SM.
#define P2_X3S  0
#define P2_AS   26624
#define P2_SMEM (26624 + 20864)

__global__ void __launch_bounds__(256, 4)
k_p2(float* __restrict__ out) {
    extern __shared__ __align__(16) char smraw[];
    float* x3s = (float*)(smraw + P2_X3S);
    float* as_ = (float*)(smraw + P2_AS);

    int tt0   = blockIdx.x * 32;
    int obase = blockIdx.y * 8;
    int z     = blockIdx.z;
    int s     = z >> 5;
    int n     = z & 31;
    float* yout = out + (size_t)s * STREAM_ELEMS;

    int tid  = threadIdx.x;
    int wid  = tid >> 5;
    int lane = tid & 31;

    float yacc[VV];
    #pragma unroll
    for (int u = 0; u < VV; u++) yacc[u] = 0.f;

    for (int i = 0; i < SS; i++) {
        __syncthreads();
        {
            const float* srcb = &g_x3[s][i][n][obase][0] + (size_t)tt0*26;
            for (int q = tid; q < 1664; q += 256) {
                int ol = q / 208, pos = (q - ol*208) * 4;
                *(float4*)&x3s[ol*832 + pos] =
                    *(const float4*)(srcb + (size_t)ol*X3ROW + pos);
            }
        }
        {
            const float4* asrc = (const float4*)&g_a[s][i][n][obase][0];
            float4* adst = (float4*)as_;
            #pragma unroll
            for (int q = tid; q < 8*AROW/4; q += 256) adst[q] = asrc[q];
        }
        __syncthreads();

        {
            const u64* xrow = (const u64*)&x3s[wid*832 + lane*26];
            u64 xp2[12];
            #pragma unroll
            for (int j = 0; j < 12; j++) xp2[j] = xrow[j];
            float xlast = x3s[wid*832 + lane*26 + 24];
            const float* ga = &as_[wid*AROW];
            #pragma unroll
            for (int u = 0; u < VV; u++) {
                const u64* ar = (const u64*)(ga + u*26);
                u64 accA = 0ull, accB = 0ull;
                #pragma unroll
                for (int j = 0; j < 12; j += 2) {
                    ffma2(accA, ar[j],   xp2[j]);
                    ffma2(accB, ar[j+1], xp2[j+1]);
                }
                float a0, a1, b0, b1;
                unpack2(accA, a0, a1); unpack2(accB, b0, b1);
                yacc[u] += (a0 + a1) + (b0 + b1) + ga[u*26 + 24] * xlast;
            }
        }
    }

    {
        int o = obase + wid;
        float ls = 0.f, lq = 0.f;
        #pragma unroll
        for (int u = 0; u < VV; u++) { float yv = yacc[u]; ls += yv; lq += yv*yv; }
        #pragma unroll
        for (int off = 16; off; off >>= 1) {
            ls += __shfl_down_sync(0xffffffffu, ls, off);
            lq += __shfl_down_sync(0xffffffffu, lq, off);
        }
        if (lane == 0) {
            atomicAdd(&g_sum[s][o],   ls);
            atomicAdd(&g_sumsq[s][o], lq);
        }
    }

    __syncthreads();
    #pragma unroll
    for (int u = 0; u < VV; u++)
        x3s[wid*832 + lane*25 + u] = yacc[u];
    __syncthreads();
    {
        #pragma unroll
        for (int q = tid; q < 1600; q += 256) {
            int ol = q / 200, k4 = q - ol*200;
            float4 val = *(const float4*)&x3s[ol*832 + k4*4];
            float* dst = yout + (size_t)(n*OO + obase + ol)*TTT*VV + tt0*VV + k4*4;
            *(float4*)dst = val;
        }
    }
}

// ---------------- K5 ---------------------------------------------------------
__global__ void k_stats() {
    int i = threadIdx.x;
    if (i < 2*OO) {
        int s = i / OO, o = i % OO;
        float m = g_sum[s][o] * (1.0f/NTV);
        float v = g_sumsq[s][o] * (1.0f/NTV) - m*m;
        g_mean[s][o] = m;
        g_rstd[s][o] = rsqrtf(v + 1e-5f);
    }
}

// ---------------- K6: BN + residual + ReLU -----------------------------------
__global__ void k_bn(const float* __restrict__ x1, const float* __restrict__ x2,
                     const float* __restrict__ bn1w, const float* __restrict__ bn1b,
                     const float* __restrict__ bn2w, const float* __restrict__ bn2b,
                     float* __restrict__ out) {
    const long total4 = 2L * STREAM_ELEMS / 4;
    long stride = (long)gridDim.x * blockDim.x;
    for (long q = (long)blockIdx.x * blockDim.x + threadIdx.x; q < total4; q += stride) {
        long e   = q * 4;
        int  s   = (int)(e / STREAM_ELEMS);
        long rem = e % STREAM_ELEMS;
        int  o   = (int)((rem / (TTT*VV)) % OO);
        const float* bw = s ? bn2w : bn1w;
        const float* bb = s ? bn2b : bn1b;
        const float* xr = s ? x2   : x1;
        float m  = g_mean[s][o], rs = g_rstd[s][o];
        float sc = rs * bw[o];
        float sh = bb[o] - m * sc;
        float4 yv = ((float4*)out)[q];
        float4 xv = ((const float4*)xr)[rem/4];
        yv.x = fmaxf(fmaf(yv.x, sc, sh) + xv.x, 0.f);
        yv.y = fmaxf(fmaf(yv.y, sc, sh) + xv.y, 0.f);
        yv.z = fmaxf(fmaf(yv.z, sc, sh) + xv.z, 0.f);
        yv.w = fmaxf(fmaf(yv.w, sc, sh) + xv.w, 0.f);
        ((float4*)out)[q] = yv;
    }
}

// ---------------- launcher ---------------------------------------------------
extern "C" void kernel_launch(void* const* d_in, const int* in_sizes, int n_in,
                              void* d_out, int out_size) {
    const float* x1    = (const float*)d_in[0];
    const float* x2    = (const float*)d_in[1];
    const float* PA    = (const float*)d_in[2];
    const float* alpha = (const float*)d_in[3];
    const float* c1w   = (const float*)d_in[4];
    const float* c1b   = (const float*)d_in[5];
    const float* c2w   = (const float*)d_in[6];
    const float* c2b   = (const float*)d_in[7];
    const float* c3w   = (const float*)d_in[8];
    const float* c3b   = (const float*)d_in[9];
    const float* c4w   = (const float*)d_in[10];
    const float* c4b   = (const float*)d_in[11];
    const float* c5w   = (const float*)d_in[12];
    const float* c5b   = (const float*)d_in[13];
    const float* c6w   = (const float*)d_in[14];
    const float* c6b   = (const float*)d_in[15];
    const float* bn1w  = (const float*)d_in[16];
    const float* bn1b  = (const float*)d_in[17];
    const float* bn2w  = (const float*)d_in[18];
    const float* bn2b  = (const float*)d_in[19];
    float* out = (float*)d_out;

    cudaFuncSetAttribute(k_conv, cudaFuncAttributeMaxDynamicSharedMemorySize, CONV_SMEM);
    cudaFuncSetAttribute(k_p2,   cudaFuncAttributeMaxDynamicSharedMemorySize, P2_SMEM);

    k_mean<<<2*NN*CC, 800>>>(x1, x2);
    k_r<<<SS*NN, 512>>>(c1w, c1b, c2w, c2b);
    k_a<<<dim3(4, SS*NN), 256>>>(PA, alpha, c5w, c5b, c6w, c6b);
    k_conv<<<dim3(16, NN, 2), 512, CONV_SMEM>>>(x1, x2, c3w, c3b, c4w, c4b);
    k_p2<<<dim3(TTT/32, OO/8, 2*NN), 256, P2_SMEM>>>(out);
    k_stats<<<1, 128>>>();
    k_bn<<<8192, 256>>>(x1, x2, bn1w, bn1b, bn2w, bn2b, out);
}